// round 2
// baseline (speedup 1.0000x reference)
#include <cuda_runtime.h>
#include <cstdint>

#define M_OUT 2049
#define MPAD  2112
#define NSIG  4096
#define KDIM  4096

// c = float(-2.0*3.14/4096) exactly as JAX computes it (double scalar -> f32 cast)
static constexpr float CANG = (float)(-2.0 * 3.14 / 4096.0);
static constexpr float DEN  = (float)(4096.0 / 30.0);

__device__ float g_mean[KDIM];
__device__ float2 g_w2[(size_t)MPAD * KDIM];             // (cos, sin) table, rows >= 2049 zero
__device__ unsigned long long g_best[M_OUT];

// ---------- packed f32x2 helpers ----------
__device__ __forceinline__ void unpack2(unsigned long long v, float& lo, float& hi) {
    asm("mov.b64 {%0, %1}, %2;" : "=f"(lo), "=f"(hi) : "l"(v));
}
__device__ __forceinline__ unsigned long long ffma2(unsigned long long a,
                                                    unsigned long long b,
                                                    unsigned long long c) {
    asm("fma.rn.f32x2 %0, %1, %2, %0;" : "+l"(c) : "l"(a), "l"(b));
    return c;
}

// ---------- kernel 1: per-row means ----------
__global__ void mean_kernel(const float* __restrict__ x) {
    __shared__ float red[256];
    const int n = blockIdx.x;
    const float4* row = (const float4*)(x + (size_t)n * NSIG);
    float s = 0.f;
#pragma unroll
    for (int c = 0; c < 4; ++c) {
        float4 v = row[threadIdx.x + c * 256];
        s += (v.x + v.y) + (v.z + v.w);
    }
    red[threadIdx.x] = s;
    __syncthreads();
    for (int off = 128; off > 0; off >>= 1) {
        if (threadIdx.x < off) red[threadIdx.x] += red[threadIdx.x + off];
        __syncthreads();
    }
    if (threadIdx.x == 0) g_mean[n] = red[0] * (1.0f / 4096.0f);
}

// ---------- kernel 2: trig table + reset argmax state ----------
// Accurate fp32 sincos: fp32 angle (matching reference), 3-term Cody-Waite FMA
// reduction (no fp64 anywhere), minimax fp32 polynomials (~1-2 ulp).
__global__ void trig_kernel() {
    const long long idx = (long long)blockIdx.x * blockDim.x + threadIdx.x;
    if (idx >= (long long)MPAD * KDIM) return;
    const int i = (int)(idx >> 12);
    const int n = (int)(idx & 4095);
    float2 w;
    if (i < M_OUT) {
        const float t = (float)(i * n);          // exact (< 2^23)
        const float a = CANG * t;                // one rounding, same as reference
        const float kf = rintf(a * 0.63661977236758134f); // a * 2/pi, |kf| <= 8187
        const int   k  = (int)kf;
        // 3-term Cody-Waite: pi/2 = C1 + C2 + C3 (CUDA libm constants)
        float r = fmaf(kf, -1.57079601287841796875f,   a);
        r       = fmaf(kf, -3.1391647326017916e-07f,   r);
        r       = fmaf(kf, -5.3903025299577648e-15f,   r);
        const float z = r * r;
        const float sinp = r * fmaf(z, fmaf(z, fmaf(z, -1.9515295891e-4f,
                                                8.3321608736e-3f),
                                        -1.6666654611e-1f), 1.0f);
        const float cosp = fmaf(z, fmaf(z, fmaf(z, fmaf(z, 2.443315711809948e-5f,
                                                    -1.388731625493765e-3f),
                                            4.166664568298827e-2f),
                                    -0.5f), 1.0f);
        const int q = k & 3;
        float c, s;
        if (q == 0)      { c =  cosp; s =  sinp; }
        else if (q == 1) { c = -sinp; s =  cosp; }
        else if (q == 2) { c = -cosp; s = -sinp; }
        else             { c =  sinp; s = -cosp; }
        w = make_float2(c, s);
    } else {
        w = make_float2(0.f, 0.f);
    }
    g_w2[idx] = w;
    if (idx < M_OUT) g_best[idx] = 0ull;
}

// ---------- kernel 3: dual GEMM (cos & sin via packed f32x2) + fused argmax ----------
__global__ __launch_bounds__(256, 2) void gemm_argmax_kernel(const float* __restrict__ x) {
    __shared__ float2 As[16][66];                 // (cos,sin) pairs, [k][i]
    __shared__ float2 Bs[16][68];                 // (b, b) duplicated pairs, [k][j]
    __shared__ unsigned long long sbest[64];

    const int tid = threadIdx.x;
    const int i0 = blockIdx.y * 64;
    const int j0 = blockIdx.x * 64;

    // loader mapping
    const int ai = tid & 63;            // A row (i)
    const int ak = (tid >> 6) << 2;     // A k offset (0,4,8,12)
    const int bk = tid >> 4;            // B k row (0..15)
    const int bj = (tid & 15) << 2;     // B col offset
    // compute mapping
    const int tx4 = (tid & 15) << 2;
    const int ty4 = (tid >> 4) << 2;

    if (tid < 64) sbest[tid] = 0ull;

    const float2* __restrict__ wrow = g_w2 + (size_t)(i0 + ai) * KDIM;

    unsigned long long acc[4][4];
#pragma unroll
    for (int a = 0; a < 4; ++a)
#pragma unroll
        for (int b = 0; b < 4; ++b) acc[a][b] = 0ull;

    // prefetch tile 0
    float4 pa0 = *(const float4*)(wrow + ak);
    float4 pa1 = *(const float4*)(wrow + ak + 2);
    float4 pb  = *(const float4*)(x + (size_t)bk * NSIG + (j0 + bj));
    float  pm  = g_mean[bk];

    for (int kt = 0; kt < KDIM / 16; ++kt) {
        As[ak + 0][ai] = make_float2(pa0.x, pa0.y);
        As[ak + 1][ai] = make_float2(pa0.z, pa0.w);
        As[ak + 2][ai] = make_float2(pa1.x, pa1.y);
        As[ak + 3][ai] = make_float2(pa1.z, pa1.w);
        {
            const float b0 = pb.x - pm, b1 = pb.y - pm, b2 = pb.z - pm, b3 = pb.w - pm;
            *(float4*)(&Bs[bk][bj])     = make_float4(b0, b0, b1, b1);
            *(float4*)(&Bs[bk][bj + 2]) = make_float4(b2, b2, b3, b3);
        }
        __syncthreads();

        if (kt + 1 < KDIM / 16) {
            const int kbase = (kt + 1) * 16;
            pa0 = *(const float4*)(wrow + kbase + ak);
            pa1 = *(const float4*)(wrow + kbase + ak + 2);
            pb  = *(const float4*)(x + (size_t)(kbase + bk) * NSIG + (j0 + bj));
            pm  = g_mean[kbase + bk];
        }

#pragma unroll
        for (int kk = 0; kk < 16; ++kk) {
            const ulonglong2* ap = (const ulonglong2*)(&As[kk][ty4]);
            const ulonglong2 a01 = ap[0];
            const ulonglong2 a23 = ap[1];
            const ulonglong2* bp = (const ulonglong2*)(&Bs[kk][tx4]);
            const ulonglong2 b01 = bp[0];
            const ulonglong2 b23 = bp[1];
            acc[0][0] = ffma2(a01.x, b01.x, acc[0][0]);
            acc[0][1] = ffma2(a01.x, b01.y, acc[0][1]);
            acc[0][2] = ffma2(a01.x, b23.x, acc[0][2]);
            acc[0][3] = ffma2(a01.x, b23.y, acc[0][3]);
            acc[1][0] = ffma2(a01.y, b01.x, acc[1][0]);
            acc[1][1] = ffma2(a01.y, b01.y, acc[1][1]);
            acc[1][2] = ffma2(a01.y, b23.x, acc[1][2]);
            acc[1][3] = ffma2(a01.y, b23.y, acc[1][3]);
            acc[2][0] = ffma2(a23.x, b01.x, acc[2][0]);
            acc[2][1] = ffma2(a23.x, b01.y, acc[2][1]);
            acc[2][2] = ffma2(a23.x, b23.x, acc[2][2]);
            acc[2][3] = ffma2(a23.x, b23.y, acc[2][3]);
            acc[3][0] = ffma2(a23.y, b01.x, acc[3][0]);
            acc[3][1] = ffma2(a23.y, b01.y, acc[3][1]);
            acc[3][2] = ffma2(a23.y, b23.x, acc[3][2]);
            acc[3][3] = ffma2(a23.y, b23.y, acc[3][3]);
        }
        __syncthreads();
    }

    // fused argmax epilogue: amp^2 = re^2 + im^2 (sqrt & /Ns are monotone)
#pragma unroll
    for (int ti = 0; ti < 4; ++ti) {
        float bestv = -1.0f;
        unsigned bestj = 0;
#pragma unroll
        for (int tj = 0; tj < 4; ++tj) {
            float re, im;
            unpack2(acc[ti][tj], re, im);
            const float v = fmaf(re, re, im * im);
            const unsigned j = (unsigned)(j0 + tx4 + tj);
            if (v > bestv) { bestv = v; bestj = j; }   // ascending j: ties keep smallest j
        }
        const unsigned long long p =
            ((unsigned long long)__float_as_uint(bestv) << 32) |
            (unsigned long long)(0xFFFFFFFFu - bestj);          // ties -> smaller j wins
        atomicMax(&sbest[ty4 + ti], p);
    }
    __syncthreads();
    if (tid < 64) {
        const int gi = i0 + tid;
        if (gi < M_OUT) atomicMax(&g_best[gi], sbest[tid]);
    }
}

// ---------- kernel 4: map argmax index -> heart rate ----------
__global__ void final_kernel(float* __restrict__ out) {
    const int i = blockIdx.x * blockDim.x + threadIdx.x;
    if (i < M_OUT) {
        const unsigned j = 0xFFFFFFFFu - (unsigned)(g_best[i] & 0xFFFFFFFFull);
        const float freq = (float)j / DEN;     // matches jnp.arange(Ns)/(Ns/FPS)
        out[i] = freq * 60.0f;
    }
}

extern "C" void kernel_launch(void* const* d_in, const int* in_sizes, int n_in,
                              void* d_out, int out_size) {
    const float* x = (const float*)d_in[0];
    float* out = (float*)d_out;

    mean_kernel<<<KDIM, 256>>>(x);

    const long long trig_total = (long long)MPAD * KDIM;
    trig_kernel<<<(unsigned)((trig_total + 255) / 256), 256>>>();

    dim3 grid(NSIG / 64, MPAD / 64);   // 64 x 33
    gemm_argmax_kernel<<<grid, 256>>>(x);

    final_kernel<<<(M_OUT + 255) / 256, 256>>>(out);
}

// round 5
// speedup vs baseline: 1.8135x; 1.8135x over previous
#include <cuda_runtime.h>
#include <cstdint>

#define M_OUT 2049
#define MPAD  2112
#define NSIG  4096
#define KDIM  4096

// c = float(-2.0*3.14/4096) exactly as JAX computes it (double scalar -> f32 cast)
static constexpr float CANG = (float)(-2.0 * 3.14 / 4096.0);
static constexpr float DEN  = (float)(4096.0 / 30.0);

__device__ float g_mean[KDIM];
__device__ float2 g_w2[(size_t)MPAD * KDIM];             // (cos, sin) table, rows >= 2049 zero
__device__ unsigned long long g_best[M_OUT];

// ---------- packed f32x2 helpers ----------
__device__ __forceinline__ unsigned long long pack2(float lo, float hi) {
    unsigned long long r;
    asm("mov.b64 %0, {%1, %2};" : "=l"(r) : "f"(lo), "f"(hi));
    return r;
}
__device__ __forceinline__ void unpack2(unsigned long long v, float& lo, float& hi) {
    asm("mov.b64 {%0, %1}, %2;" : "=f"(lo), "=f"(hi) : "l"(v));
}
__device__ __forceinline__ unsigned long long ffma2(unsigned long long a,
                                                    unsigned long long b,
                                                    unsigned long long c) {
    asm("fma.rn.f32x2 %0, %1, %2, %0;" : "+l"(c) : "l"(a), "l"(b));
    return c;
}

// ---------- kernel 1: per-row means ----------
__global__ void mean_kernel(const float* __restrict__ x) {
    __shared__ float red[256];
    const int n = blockIdx.x;
    const float4* row = (const float4*)(x + (size_t)n * NSIG);
    float s = 0.f;
#pragma unroll
    for (int c = 0; c < 4; ++c) {
        float4 v = row[threadIdx.x + c * 256];
        s += (v.x + v.y) + (v.z + v.w);
    }
    red[threadIdx.x] = s;
    __syncthreads();
    for (int off = 128; off > 0; off >>= 1) {
        if (threadIdx.x < off) red[threadIdx.x] += red[threadIdx.x + off];
        __syncthreads();
    }
    if (threadIdx.x == 0) g_mean[n] = red[0] * (1.0f / 4096.0f);
}

// ---------- kernel 2: trig table + reset argmax state ----------
// Accurate fp32 sincos: fp32 angle (matching reference), 3-term Cody-Waite FMA
// reduction (no fp64 anywhere), minimax fp32 polynomials (~1-2 ulp).
__global__ void trig_kernel() {
    const long long idx = (long long)blockIdx.x * blockDim.x + threadIdx.x;
    if (idx >= (long long)MPAD * KDIM) return;
    const int i = (int)(idx >> 12);
    const int n = (int)(idx & 4095);
    float2 w;
    if (i < M_OUT) {
        const float t = (float)(i * n);          // exact (< 2^23)
        const float a = CANG * t;                // one rounding, same as reference
        const float kf = rintf(a * 0.63661977236758134f); // a * 2/pi, |kf| <= 8187
        const int   k  = (int)kf;
        // 3-term Cody-Waite: pi/2 = C1 + C2 + C3 (CUDA libm constants)
        float r = fmaf(kf, -1.57079601287841796875f,   a);
        r       = fmaf(kf, -3.1391647326017916e-07f,   r);
        r       = fmaf(kf, -5.3903025299577648e-15f,   r);
        const float z = r * r;
        const float sinp = r * fmaf(z, fmaf(z, fmaf(z, -1.9515295891e-4f,
                                                8.3321608736e-3f),
                                        -1.6666654611e-1f), 1.0f);
        const float cosp = fmaf(z, fmaf(z, fmaf(z, fmaf(z, 2.443315711809948e-5f,
                                                    -1.388731625493765e-3f),
                                            4.166664568298827e-2f),
                                    -0.5f), 1.0f);
        const int q = k & 3;
        float c, s;
        if (q == 0)      { c =  cosp; s =  sinp; }
        else if (q == 1) { c = -sinp; s =  cosp; }
        else if (q == 2) { c = -cosp; s = -sinp; }
        else             { c =  sinp; s = -cosp; }
        w = make_float2(c, s);
    } else {
        w = make_float2(0.f, 0.f);
    }
    g_w2[idx] = w;
    if (idx < M_OUT) g_best[idx] = 0ull;
}

// ---------- kernel 3: dual GEMM (cos & sin via packed f32x2) + fused argmax ----------
// Inner loop identical to round-1 (known-good codegen): B read as float4 from
// smem and packed to (b,b) pairs in registers.
__global__ __launch_bounds__(256, 2) void gemm_argmax_kernel(const float* __restrict__ x) {
    __shared__ float2 As[16][66];                 // (cos,sin) pairs, [k][i]
    __shared__ float  Bs[16][68];                 // [k][j]
    __shared__ unsigned long long sbest[64];

    const int tid = threadIdx.x;
    const int i0 = blockIdx.y * 64;
    const int j0 = blockIdx.x * 64;

    // loader mapping
    const int ai = tid & 63;            // A row (i)
    const int ak = (tid >> 6) << 2;     // A k offset (0,4,8,12)
    const int bk = tid >> 4;            // B k row (0..15)
    const int bj = (tid & 15) << 2;     // B col offset
    // compute mapping
    const int tx4 = (tid & 15) << 2;
    const int ty4 = (tid >> 4) << 2;

    if (tid < 64) sbest[tid] = 0ull;

    const float2* __restrict__ wrow = g_w2 + (size_t)(i0 + ai) * KDIM;

    unsigned long long acc[4][4];
#pragma unroll
    for (int a = 0; a < 4; ++a)
#pragma unroll
        for (int b = 0; b < 4; ++b) acc[a][b] = 0ull;

    // prefetch tile 0
    float4 pa0 = *(const float4*)(wrow + ak);
    float4 pa1 = *(const float4*)(wrow + ak + 2);
    float4 pb  = *(const float4*)(x + (size_t)bk * NSIG + (j0 + bj));
    float  pm  = g_mean[bk];

    for (int kt = 0; kt < KDIM / 16; ++kt) {
        As[ak + 0][ai] = make_float2(pa0.x, pa0.y);
        As[ak + 1][ai] = make_float2(pa0.z, pa0.w);
        As[ak + 2][ai] = make_float2(pa1.x, pa1.y);
        As[ak + 3][ai] = make_float2(pa1.z, pa1.w);
        *(float4*)(&Bs[bk][bj]) = make_float4(pb.x - pm, pb.y - pm, pb.z - pm, pb.w - pm);
        __syncthreads();

        if (kt + 1 < KDIM / 16) {
            const int kbase = (kt + 1) * 16;
            pa0 = *(const float4*)(wrow + kbase + ak);
            pa1 = *(const float4*)(wrow + kbase + ak + 2);
            pb  = *(const float4*)(x + (size_t)(kbase + bk) * NSIG + (j0 + bj));
            pm  = g_mean[kbase + bk];
        }

#pragma unroll
        for (int kk = 0; kk < 16; ++kk) {
            const ulonglong2* ap = (const ulonglong2*)(&As[kk][ty4]);
            const ulonglong2 a01 = ap[0];
            const ulonglong2 a23 = ap[1];
            const float4 b4 = *(const float4*)(&Bs[kk][tx4]);
            const unsigned long long b0 = pack2(b4.x, b4.x);
            const unsigned long long b1 = pack2(b4.y, b4.y);
            const unsigned long long b2 = pack2(b4.z, b4.z);
            const unsigned long long b3 = pack2(b4.w, b4.w);
            acc[0][0] = ffma2(a01.x, b0, acc[0][0]);
            acc[0][1] = ffma2(a01.x, b1, acc[0][1]);
            acc[0][2] = ffma2(a01.x, b2, acc[0][2]);
            acc[0][3] = ffma2(a01.x, b3, acc[0][3]);
            acc[1][0] = ffma2(a01.y, b0, acc[1][0]);
            acc[1][1] = ffma2(a01.y, b1, acc[1][1]);
            acc[1][2] = ffma2(a01.y, b2, acc[1][2]);
            acc[1][3] = ffma2(a01.y, b3, acc[1][3]);
            acc[2][0] = ffma2(a23.x, b0, acc[2][0]);
            acc[2][1] = ffma2(a23.x, b1, acc[2][1]);
            acc[2][2] = ffma2(a23.x, b2, acc[2][2]);
            acc[2][3] = ffma2(a23.x, b3, acc[2][3]);
            acc[3][0] = ffma2(a23.y, b0, acc[3][0]);
            acc[3][1] = ffma2(a23.y, b1, acc[3][1]);
            acc[3][2] = ffma2(a23.y, b2, acc[3][2]);
            acc[3][3] = ffma2(a23.y, b3, acc[3][3]);
        }
        __syncthreads();
    }

    // fused argmax epilogue: amp^2 = re^2 + im^2 (sqrt & /Ns are monotone)
#pragma unroll
    for (int ti = 0; ti < 4; ++ti) {
        float bestv = -1.0f;
        unsigned bestj = 0;
#pragma unroll
        for (int tj = 0; tj < 4; ++tj) {
            float re, im;
            unpack2(acc[ti][tj], re, im);
            const float v = fmaf(re, re, im * im);
            const unsigned j = (unsigned)(j0 + tx4 + tj);
            if (v > bestv) { bestv = v; bestj = j; }   // ascending j: ties keep smallest j
        }
        const unsigned long long p =
            ((unsigned long long)__float_as_uint(bestv) << 32) |
            (unsigned long long)(0xFFFFFFFFu - bestj);          // ties -> smaller j wins
        atomicMax(&sbest[ty4 + ti], p);
    }
    __syncthreads();
    if (tid < 64) {
        const int gi = i0 + tid;
        if (gi < M_OUT) atomicMax(&g_best[gi], sbest[tid]);
    }
}

// ---------- kernel 4: map argmax index -> heart rate ----------
__global__ void final_kernel(float* __restrict__ out) {
    const int i = blockIdx.x * blockDim.x + threadIdx.x;
    if (i < M_OUT) {
        const unsigned j = 0xFFFFFFFFu - (unsigned)(g_best[i] & 0xFFFFFFFFull);
        const float freq = (float)j / DEN;     // matches jnp.arange(Ns)/(Ns/FPS)
        out[i] = freq * 60.0f;
    }
}

extern "C" void kernel_launch(void* const* d_in, const int* in_sizes, int n_in,
                              void* d_out, int out_size) {
    const float* x = (const float*)d_in[0];
    float* out = (float*)d_out;

    mean_kernel<<<KDIM, 256>>>(x);

    const long long trig_total = (long long)MPAD * KDIM;
    trig_kernel<<<(unsigned)((trig_total + 255) / 256), 256>>>();

    dim3 grid(NSIG / 64, MPAD / 64);   // 64 x 33
    gemm_argmax_kernel<<<grid, 256>>>(x);

    final_kernel<<<(M_OUT + 255) / 256, 256>>>(out);
}